// round 14
// baseline (speedup 1.0000x reference)
#include <cuda_runtime.h>
#include <cuda_bf16.h>
#include <cuda_fp16.h>

#define B     64
#define S     512
#define TF    1024
#define TD    128
#define V     1000
#define KW    31
#define PAD   15
#define TT    16   // t-tile in scores kernel
#define NTILE 8    // t-tiles per scores block

typedef unsigned long long u64;

// ---------------- scratch (device globals; no allocation allowed) ----------------
__device__ __half g_keysTh[(size_t)B * S * TF];  // keys transposed fp16: [b][s][t]
__device__ __half g_featH[(size_t)B * TF * S];   // features fp16 copy: [b][t][d]
__device__ float g_hbuf[2][B * S];              // double-buffered h (parity by step)
__device__ float g_ctxP[4][B * S];              // ctx t-quarter partials
__device__ float g_w[B * TF];
__device__ float g_scores[B * TF];
__device__ float g_cwT[KW * S];                 // conv filters transposed: [k][s]
__device__ float g_qbias[S];                    // bq + conv_b
// split-K partial buffers (written whole each step; no zeroing needed)
__device__ float g_giP[8][B * 3 * S];
__device__ float g_ghP[4][B * 3 * S];
__device__ float g_qP[8][B * S];
__device__ float g_loP[8][B * V];

// ---------------- f32x2 / fp16 helpers ----------------
__device__ __forceinline__ u64 pack2(float lo, float hi) {
    u64 r; asm("mov.b64 %0, {%1,%2};" : "=l"(r) : "f"(lo), "f"(hi)); return r;
}
__device__ __forceinline__ void unpack2(u64 v, float& lo, float& hi) {
    asm("mov.b64 {%0,%1}, %2;" : "=f"(lo), "=f"(hi) : "l"(v));
}
__device__ __forceinline__ u64 add2(u64 a, u64 b) {
    u64 r; asm("add.rn.f32x2 %0, %1, %2;" : "=l"(r) : "l"(a), "l"(b)); return r;
}
__device__ __forceinline__ u64 fma2(u64 a, u64 b, u64 c) {
    u64 r; asm("fma.rn.f32x2 %0, %1, %2, %3;" : "=l"(r) : "l"(a), "l"(b), "l"(c)); return r;
}
__device__ __forceinline__ void h2f(unsigned u, float& lo, float& hi) {
    __half2 h = *reinterpret_cast<__half2*>(&u);
    float2 f = __half22float2(h);
    lo = f.x; hi = f.y;
}

// exact-ish tanh/sigmoid (GRU path — recurrence-sensitive)
__device__ __forceinline__ float fast_tanh(float x) {
    float e = __expf(2.0f * x);
    return 1.0f - __fdividef(2.0f, e + 1.0f);
}
__device__ __forceinline__ float fast_sigmoid(float x) {
    return __fdividef(1.0f, 1.0f + __expf(-x));
}
// HW tanh (scores path only)
__device__ __forceinline__ float tanha(float x) {
    float y; asm("tanh.approx.f32 %0, %1;" : "=f"(y) : "f"(x)); return y;
}

// ---------------- init: zero recurrent state ----------------
__global__ void init_kernel() {
    int idx = blockIdx.x * 256 + threadIdx.x;
    if (idx < B * S) {
        g_hbuf[0][idx] = 0.0f; g_hbuf[1][idx] = 0.0f;
        g_ctxP[0][idx] = 0.0f; g_ctxP[1][idx] = 0.0f;
        g_ctxP[2][idx] = 0.0f; g_ctxP[3][idx] = 0.0f;
    }
    if (idx < B * TF) g_w[idx] = 0.0f;
}

// ---------------- features -> fp16 copy (one-time) ----------------
__global__ __launch_bounds__(256) void feat_convert_kernel(const float* __restrict__ features) {
    size_t idx = (size_t)blockIdx.x * 256 + threadIdx.x;   // over elements/4
    float4 v = *(const float4*)(features + idx * 4);
    __half2 lo = __floats2half2_rn(v.x, v.y);
    __half2 hi = __floats2half2_rn(v.z, v.w);
    uint2 o;
    o.x = *(unsigned*)&lo; o.y = *(unsigned*)&hi;
    *(uint2*)(g_featH + idx * 4) = o;
}

// ---------------- transpose conv filters + qbias ----------------
__global__ void cw_transpose_kernel(const float* __restrict__ conv_w,
                                    const float* __restrict__ bq,
                                    const float* __restrict__ conv_b) {
    int idx = blockIdx.x * 256 + threadIdx.x;
    if (idx < S * KW) {
        int s = idx / KW, k = idx % KW;
        g_cwT[k * S + s] = conv_w[idx];
    }
    if (idx < S) g_qbias[idx] = bq[idx] + conv_b[idx];
}

// ---------------- keys precompute -> fp16 keysT ----------------
__global__ __launch_bounds__(256) void keys_gemm_kernel(
    const float* __restrict__ features, const float* __restrict__ Wk,
    const float* __restrict__ bk)
{
    __shared__ float As[16][68];
    __shared__ float Bs[16][68];
    int tid = threadIdx.x;
    int m0 = blockIdx.x * 64, n0 = blockIdx.y * 64;
    int lr = tid & 63, lk = tid >> 6;
    int tx = tid & 15, ty = tid >> 4;
    float c[4][4] = {};

    for (int k0 = 0; k0 < S; k0 += 16) {
        float4 a = *(const float4*)(features + (size_t)(m0 + lr) * S + k0 + lk * 4);
        float4 bv = *(const float4*)(Wk + (size_t)(n0 + lr) * S + k0 + lk * 4);
        __syncthreads();
        As[lk * 4 + 0][lr] = a.x;  As[lk * 4 + 1][lr] = a.y;
        As[lk * 4 + 2][lr] = a.z;  As[lk * 4 + 3][lr] = a.w;
        Bs[lk * 4 + 0][lr] = bv.x; Bs[lk * 4 + 1][lr] = bv.y;
        Bs[lk * 4 + 2][lr] = bv.z; Bs[lk * 4 + 3][lr] = bv.w;
        __syncthreads();
#pragma unroll
        for (int k = 0; k < 16; k++) {
            float4 av = *(const float4*)&As[k][ty * 4];
            float4 bw = *(const float4*)&Bs[k][tx * 4];
            c[0][0] = fmaf(av.x, bw.x, c[0][0]); c[0][1] = fmaf(av.x, bw.y, c[0][1]);
            c[0][2] = fmaf(av.x, bw.z, c[0][2]); c[0][3] = fmaf(av.x, bw.w, c[0][3]);
            c[1][0] = fmaf(av.y, bw.x, c[1][0]); c[1][1] = fmaf(av.y, bw.y, c[1][1]);
            c[1][2] = fmaf(av.y, bw.z, c[1][2]); c[1][3] = fmaf(av.y, bw.w, c[1][3]);
            c[2][0] = fmaf(av.z, bw.x, c[2][0]); c[2][1] = fmaf(av.z, bw.y, c[2][1]);
            c[2][2] = fmaf(av.z, bw.z, c[2][2]); c[2][3] = fmaf(av.z, bw.w, c[2][3]);
            c[3][0] = fmaf(av.w, bw.x, c[3][0]); c[3][1] = fmaf(av.w, bw.y, c[3][1]);
            c[3][2] = fmaf(av.w, bw.z, c[3][2]); c[3][3] = fmaf(av.w, bw.w, c[3][3]);
        }
    }
    int bb = m0 >> 10;
    int tbase = (m0 & 1023) + ty * 4;
#pragma unroll
    for (int j = 0; j < 4; j++) {
        int n = n0 + tx * 4 + j;
        float bias = bk[n];
        __half* dst = g_keysTh + ((size_t)bb * S + n) * TF + tbase;
        __half2 p0 = __floats2half2_rn(c[0][j] + bias, c[1][j] + bias);
        __half2 p1 = __floats2half2_rn(c[2][j] + bias, c[3][j] + bias);
        *(__half2*)(dst) = p0;
        *(__half2*)(dst + 2) = p1;
    }
}

// ---------------- fused h-update + q-GEMM + logits-finalize ----------------
// grid (9, 8), 256 thr.
//  bx < 8: q-gemm block, n0 = bx*64, k-slice sl = by (64 k's).
//          Phase 1: compute h_t[64b x 64k] inline from gate partials (exact GRU
//          math, identical in every block -> deterministic). bx==0 persists h
//          to g_hbuf[wpar]. Phase 2: q partial = sH @ Wq_slice^T -> g_qP[sl].
//  bx == 8: logits finalize of step t_fin (partition by), reads g_loP.
__global__ __launch_bounds__(256) void hq_kernel(
    const float* __restrict__ Wq, float* __restrict__ outs,
    const float* __restrict__ bo, const float* __restrict__ b_ih,
    const float* __restrict__ b_hh, int t_fin, int wpar)
{
    int tid = threadIdx.x;

    if (blockIdx.x == 8) {
        if (t_fin >= 0) {
            int part = blockIdx.y;          // 0..7, 8000 elems each
            int e_end = (part + 1) * 8000;
#pragma unroll 4
            for (int i = 0; i < 32; i++) {
                int e = part * 8000 + i * 256 + tid;
                if (e < e_end) {
                    int b = e / V, n = e - b * V;
                    float sv = bo[n];
#pragma unroll
                    for (int sl2 = 0; sl2 < 8; sl2++) sv += g_loP[sl2][e];
                    outs[((size_t)b * TD + t_fin) * V + n] = sv;
                }
            }
        }
        return;
    }

    int sl = blockIdx.y;
    int n0 = blockIdx.x * 64;
    __shared__ float sH[64][68];        // h slice: [b][k_local], 16B-aligned rows
    __shared__ float As[16][68];
    __shared__ float Bs[16][68];

    // ---- Phase 1: h for k-slice [sl*64, sl*64+64), all 64 b ----
    {
        int jb = tid & 63;
        int j = sl * 64 + jb;
        int b0 = tid >> 6;
        float bi_r = b_ih[j],        bh_r = b_hh[j];
        float bi_z = b_ih[512 + j],  bh_z = b_hh[512 + j];
        float bi_n = b_ih[1024 + j], bh_n = b_hh[1024 + j];
#pragma unroll 4
        for (int bi = 0; bi < 16; bi++) {
            int b = b0 + bi * 4;
            int base = b * (3 * S);
            float gir = 0.f, giz = 0.f, gin = 0.f;
#pragma unroll
            for (int s2 = 0; s2 < 8; s2++) {
                gir += g_giP[s2][base + j];
                giz += g_giP[s2][base + 512 + j];
                gin += g_giP[s2][base + 1024 + j];
            }
            float ghr = 0.f, ghz = 0.f, ghn = 0.f;
#pragma unroll
            for (int s2 = 0; s2 < 4; s2++) {
                ghr += g_ghP[s2][base + j];
                ghz += g_ghP[s2][base + 512 + j];
                ghn += g_ghP[s2][base + 1024 + j];
            }
            float r = fast_sigmoid(gir + bi_r + ghr + bh_r);
            float z = fast_sigmoid(giz + bi_z + ghz + bh_z);
            float n = fast_tanh(gin + bi_n + r * (ghn + bh_n));
            float ho = g_hbuf[wpar ^ 1][b * S + j];
            float hn = (1.0f - z) * n + z * ho;
            sH[b][jb] = hn;
            if (blockIdx.x == 0) g_hbuf[wpar][b * S + j] = hn;
        }
    }
    __syncthreads();

    // ---- Phase 2: q partial = sH(64b x 64k) @ Wq[n0.., sl*64..]^T ----
    int lr = tid & 63, lk = tid >> 6;
    int tx = tid & 15, ty = tid >> 4;
    float c[4][4] = {};

    for (int kc = 0; kc < 64; kc += 16) {
        int kl = kc + lk * 4;
        float4 a = *(const float4*)&sH[lr][kl];
        float4 bv = *(const float4*)(Wq + (size_t)(n0 + lr) * S + sl * 64 + kl);
        __syncthreads();
        As[lk * 4 + 0][lr] = a.x;  As[lk * 4 + 1][lr] = a.y;
        As[lk * 4 + 2][lr] = a.z;  As[lk * 4 + 3][lr] = a.w;
        Bs[lk * 4 + 0][lr] = bv.x; Bs[lk * 4 + 1][lr] = bv.y;
        Bs[lk * 4 + 2][lr] = bv.z; Bs[lk * 4 + 3][lr] = bv.w;
        __syncthreads();
#pragma unroll
        for (int k = 0; k < 16; k++) {
            float4 av = *(const float4*)&As[k][ty * 4];
            float4 bw = *(const float4*)&Bs[k][tx * 4];
            c[0][0] = fmaf(av.x, bw.x, c[0][0]); c[0][1] = fmaf(av.x, bw.y, c[0][1]);
            c[0][2] = fmaf(av.x, bw.z, c[0][2]); c[0][3] = fmaf(av.x, bw.w, c[0][3]);
            c[1][0] = fmaf(av.y, bw.x, c[1][0]); c[1][1] = fmaf(av.y, bw.y, c[1][1]);
            c[1][2] = fmaf(av.y, bw.z, c[1][2]); c[1][3] = fmaf(av.y, bw.w, c[1][3]);
            c[2][0] = fmaf(av.z, bw.x, c[2][0]); c[2][1] = fmaf(av.z, bw.y, c[2][1]);
            c[2][2] = fmaf(av.z, bw.z, c[2][2]); c[2][3] = fmaf(av.z, bw.w, c[2][3]);
            c[3][0] = fmaf(av.w, bw.x, c[3][0]); c[3][1] = fmaf(av.w, bw.y, c[3][1]);
            c[3][2] = fmaf(av.w, bw.z, c[3][2]); c[3][3] = fmaf(av.w, bw.w, c[3][3]);
        }
    }
    int gn = n0 + tx * 4;
#pragma unroll
    for (int i = 0; i < 4; i++) {
        int m = ty * 4 + i;
        *(float4*)(&g_qP[sl][m * S + gn]) =
            make_float4(c[i][0], c[i][1], c[i][2], c[i][3]);
    }
}

// ---------------- split-K skinny GEMM: 64x64 tile, 4x4/thread, partials, NO bias ----------------
// mode 0: gi partials  = x @ W_ih^T   (Ktot=1024, Ksl=128, 8 slices, N=1536)
// mode 1: gh partials  = h @ W_hh^T   (Ktot=512,  Ksl=128, 4 slices, N=1536)
// mode 3: logits part. = [h|ctx]@Wo^T (Ktot=1024, Ksl=128, 8 slices, N=1000)
// mb=0: by<8 -> mode0 sl=by; by<12 -> mode1 sl=by-8; else mode3 sl=by-12
// mb=3: mode3 sl=by.
__global__ __launch_bounds__(256) void gemm64_kernel(
    int mb,
    const int* __restrict__ input_ids, const float* __restrict__ emb,
    const float* __restrict__ W_ih, const float* __restrict__ W_hh,
    const float* __restrict__ Wo,
    int t_gates, int par)
{
    int by = blockIdx.y;
    int mode, sl;
    if (mb == 3) { mode = 3; sl = by; }
    else {
        if (by < 8)       { mode = 0; sl = by; }
        else if (by < 12) { mode = 1; sl = by - 8; }
        else              { mode = 3; sl = by - 12; }
    }

    int N, Ktot, strideN;
    const float* Bmat;
    float* dst;
    if (mode == 0)      { N = 3*S; Ktot = 1024; Bmat = W_ih; dst = g_giP[sl]; strideN = 3*S; }
    else if (mode == 1) { N = 3*S; Ktot = 512;  Bmat = W_hh; dst = g_ghP[sl]; strideN = 3*S; }
    else                { N = V;   Ktot = 1024; Bmat = Wo;   dst = g_loP[sl]; strideN = V; }

    int n0 = blockIdx.x * 64;
    if (n0 >= N) return;

    __shared__ float As[16][68];
    __shared__ float Bs[16][68];
    __shared__ int s_idx[64];

    int tid = threadIdx.x;
    if (mode == 0 && tid < 64) s_idx[tid] = input_ids[tid * TD + t_gates];
    __syncthreads();

    const float* hsrc = g_hbuf[par];
    int lr = tid & 63, lk = tid >> 6;
    int tx = tid & 15, ty = tid >> 4;
    float c[4][4] = {};

    for (int kc = 0; kc < 128; kc += 16) {
        int kb = sl * 128 + kc + lk * 4;
        float4 a;
        if (mode == 0) {
            if (kb < 512) a = *(const float4*)(emb + (size_t)s_idx[lr] * S + kb);
            else {
                int off = lr * S + (kb - 512);
                float4 p0 = *(const float4*)(g_ctxP[0] + off);
                float4 p1 = *(const float4*)(g_ctxP[1] + off);
                float4 p2 = *(const float4*)(g_ctxP[2] + off);
                float4 p3 = *(const float4*)(g_ctxP[3] + off);
                a = make_float4((p0.x + p1.x) + (p2.x + p3.x),
                                (p0.y + p1.y) + (p2.y + p3.y),
                                (p0.z + p1.z) + (p2.z + p3.z),
                                (p0.w + p1.w) + (p2.w + p3.w));
            }
        } else if (mode == 3) {
            if (kb < 512) a = *(const float4*)(hsrc + lr * S + kb);
            else {
                int off = lr * S + (kb - 512);
                float4 p0 = *(const float4*)(g_ctxP[0] + off);
                float4 p1 = *(const float4*)(g_ctxP[1] + off);
                float4 p2 = *(const float4*)(g_ctxP[2] + off);
                float4 p3 = *(const float4*)(g_ctxP[3] + off);
                a = make_float4((p0.x + p1.x) + (p2.x + p3.x),
                                (p0.y + p1.y) + (p2.y + p3.y),
                                (p0.z + p1.z) + (p2.z + p3.z),
                                (p0.w + p1.w) + (p2.w + p3.w));
            }
        } else {
            a = *(const float4*)(hsrc + lr * S + kb);
        }

        int gn = n0 + lr;
        float4 bv = make_float4(0.f, 0.f, 0.f, 0.f);
        if (gn < N) bv = *(const float4*)(Bmat + (size_t)gn * Ktot + kb);

        __syncthreads();
        As[lk * 4 + 0][lr] = a.x;  As[lk * 4 + 1][lr] = a.y;
        As[lk * 4 + 2][lr] = a.z;  As[lk * 4 + 3][lr] = a.w;
        Bs[lk * 4 + 0][lr] = bv.x; Bs[lk * 4 + 1][lr] = bv.y;
        Bs[lk * 4 + 2][lr] = bv.z; Bs[lk * 4 + 3][lr] = bv.w;
        __syncthreads();
#pragma unroll
        for (int k = 0; k < 16; k++) {
            float4 av = *(const float4*)&As[k][ty * 4];
            float4 bw = *(const float4*)&Bs[k][tx * 4];
            c[0][0] = fmaf(av.x, bw.x, c[0][0]); c[0][1] = fmaf(av.x, bw.y, c[0][1]);
            c[0][2] = fmaf(av.x, bw.z, c[0][2]); c[0][3] = fmaf(av.x, bw.w, c[0][3]);
            c[1][0] = fmaf(av.y, bw.x, c[1][0]); c[1][1] = fmaf(av.y, bw.y, c[1][1]);
            c[1][2] = fmaf(av.y, bw.z, c[1][2]); c[1][3] = fmaf(av.y, bw.w, c[1][3]);
            c[2][0] = fmaf(av.z, bw.x, c[2][0]); c[2][1] = fmaf(av.z, bw.y, c[2][1]);
            c[2][2] = fmaf(av.z, bw.z, c[2][2]); c[2][3] = fmaf(av.z, bw.w, c[2][3]);
            c[3][0] = fmaf(av.w, bw.x, c[3][0]); c[3][1] = fmaf(av.w, bw.y, c[3][1]);
            c[3][2] = fmaf(av.w, bw.z, c[3][2]); c[3][3] = fmaf(av.w, bw.w, c[3][3]);
        }
    }

    int gn = n0 + tx * 4;
    if (gn < N) {
#pragma unroll
        for (int i = 0; i < 4; i++) {
            int m = ty * 4 + i;
            *(float4*)(dst + (size_t)m * strideN + gn) =
                make_float4(c[i][0], c[i][1], c[i][2], c[i][3]);
        }
    }
}

// ---------------- epilogue: finalize logits of final step ----------------
__global__ __launch_bounds__(256) void logits_fin_kernel(
    float* __restrict__ outs, const float* __restrict__ bo)
{
    int idx = blockIdx.x * 256 + threadIdx.x;
#pragma unroll
    for (int r = 0; r < 2; r++) {
        int e = idx + r * 32768;
        if (e < B * V) {
            int b = e / V, n = e - b * V;
            float sv = bo[n];
#pragma unroll
            for (int sl = 0; sl < 8; sl++) sv += g_loP[sl][e];
            outs[((size_t)b * TD + (TD - 1)) * V + n] = sv;
        }
    }
}

// ---------------- attention scores: persistent, fp16 keys, HW tanh ----------------
__global__ __launch_bounds__(256, 2) void scores_kernel(const float* __restrict__ v_vec) {
    const int b = blockIdx.y;
    const int tg = blockIdx.x;
    const int tid = threadIdx.x;
    const int s0 = tid * 2;

    __shared__ float s_win[TT + KW - 1];   // 46
    __shared__ float s_red[8][TT + 1];

    // persistent per-block state
    u64 qv2 = *(const u64*)(g_qbias + s0);
#pragma unroll
    for (int sl = 0; sl < 8; sl++)
        qv2 = add2(qv2, *(const u64*)(&g_qP[sl][b * S + s0]));

    u64 cw2[KW];
#pragma unroll
    for (int k = 0; k < KW; k++)
        cw2[k] = *(const u64*)(g_cwT + k * S + s0);

    float2 vv = *(const float2*)(v_vec + s0);
    const __half* kp0 = g_keysTh + ((size_t)b * S + s0) * TF;

    for (int tt = 0; tt < NTILE; tt++) {
        const int t0 = tg * (NTILE * TT) + tt * TT;

        if (tid < TT + KW - 1) {
            int t = t0 + tid - PAD;
            s_win[tid] = (t >= 0 && t < TF) ? g_w[b * TF + t] : 0.0f;
        }
        __syncthreads();

        // keys fp16 -> acc (2 x uint4 per row = 16 t's)
        uint4 a0 = *(const uint4*)(kp0 + t0);
        uint4 a1 = *(const uint4*)(kp0 + t0 + 8);
        uint4 c0 = *(const uint4*)(kp0 + TF + t0);
        uint4 c1 = *(const uint4*)(kp0 + TF + t0 + 8);
        unsigned ra[8] = {a0.x, a0.y, a0.z, a0.w, a1.x, a1.y, a1.z, a1.w};
        unsigned rc[8] = {c0.x, c0.y, c0.z, c0.w, c1.x, c1.y, c1.z, c1.w};

        u64 acc[TT];
#pragma unroll
        for (int j2 = 0; j2 < 8; j2++) {
            float l0, h0, l1, h1;
            h2f(ra[j2], l0, h0);
            h2f(rc[j2], l1, h1);
            acc[2 * j2]     = add2(pack2(l0, l1), qv2);
            acc[2 * j2 + 1] = add2(pack2(h0, h1), qv2);
        }

        // diagonal-ordered conv: one broadcast per window element, packed FMA2
#pragma unroll
        for (int i = 0; i < TT + KW - 1; i++) {
            u64 wv2 = pack2(s_win[i], s_win[i]);
#pragma unroll
            for (int j = 0; j < TT; j++) {
                int k = i - j;
                if (k >= 0 && k < KW) acc[j] = fma2(cw2[k], wv2, acc[j]);
            }
        }

        // HW tanh both lanes, weight by v, reduce over s
#pragma unroll
        for (int j = 0; j < TT; j++) {
            float x0, x1; unpack2(acc[j], x0, x1);
            float cv = vv.x * tanha(x0) + vv.y * tanha(x1);
#pragma unroll
            for (int off = 16; off > 0; off >>= 1)
                cv += __shfl_xor_sync(0xffffffffu, cv, off);
            if ((tid & 31) == 0) s_red[tid >> 5][j] = cv;
        }
        __syncthreads();
        if (tid < TT) {
            float sum = 0.0f;
#pragma unroll
            for (int w = 0; w < 8; w++) sum += s_red[w][tid];
            g_scores[b * TF + t0 + tid] = sum;
        }
    }
}

// ---------------- fused softmax + context (fp16 features, t-quarter partials) ----------------
// grid (4, B), 256 threads. All 4 blocks recompute the row softmax (identical,
// deterministic); block x==0 writes g_w and ws. Each block accumulates its
// t-quarter into g_ctxP[x] for all 512 d (2 d's per thread via half2).
__global__ __launch_bounds__(256) void ctxsm_kernel(float* __restrict__ ws, int t_step)
{
    int b = blockIdx.y, x = blockIdx.x, tid = threadIdx.x;
    __shared__ float s_w[TF];
    __shared__ float s_r[8];

    float vals[4];
    float m = -1e30f;
#pragma unroll
    for (int i = 0; i < 4; i++) {
        vals[i] = g_scores[b * TF + tid + i * 256];
        m = fmaxf(m, vals[i]);
    }
#pragma unroll
    for (int off = 16; off > 0; off >>= 1)
        m = fmaxf(m, __shfl_xor_sync(0xffffffffu, m, off));
    if ((tid & 31) == 0) s_r[tid >> 5] = m;
    __syncthreads();
    m = s_r[0];
#pragma unroll
    for (int w = 1; w < 8; w++) m = fmaxf(m, s_r[w]);
    __syncthreads();

    float sum = 0.0f;
#pragma unroll
    for (int i = 0; i < 4; i++) { vals[i] = __expf(vals[i] - m); sum += vals[i]; }
#pragma unroll
    for (int off = 16; off > 0; off >>= 1)
        sum += __shfl_xor_sync(0xffffffffu, sum, off);
    if ((tid & 31) == 0) s_r[tid >> 5] = sum;
    __syncthreads();
    float total = 0.0f;
#pragma unroll
    for (int w = 0; w < 8; w++) total += s_r[w];
    float inv = __fdividef(1.0f, total);
#pragma unroll
    for (int i = 0; i < 4; i++) {
        int t = tid + i * 256;
        float wv = vals[i] * inv;
        s_w[t] = wv;
        if (x == 0) {
            g_w[b * TF + t] = wv;
            ws[((size_t)b * TD + t_step) * (size_t)TF + t] = wv;
        }
    }
    __syncthreads();

    // ctx partial: this block's t-quarter (256 t's), all 512 d (2 per thread)
    int d0 = tid * 2;
    const __half* fb = g_featH + ((size_t)b * TF + x * 256) * S + d0;
    const float* wp = s_w + x * 256;
    float p0 = 0.f, p1 = 0.f, q0 = 0.f, q1 = 0.f, r0 = 0.f, r1 = 0.f, u0 = 0.f, u1 = 0.f;
#pragma unroll 2
    for (int t = 0; t < 256; t += 4) {
        __half2 v0 = *(const __half2*)(fb + (size_t)(t + 0) * S);
        __half2 v1 = *(const __half2*)(fb + (size_t)(t + 1) * S);
        __half2 v2 = *(const __half2*)(fb + (size_t)(t + 2) * S);
        __half2 v3 = *(const __half2*)(fb + (size_t)(t + 3) * S);
        float2 f0 = __half22float2(v0);
        float2 f1 = __half22float2(v1);
        float2 f2 = __half22float2(v2);
        float2 f3 = __half22float2(v3);
        float w0 = wp[t + 0], w1 = wp[t + 1], w2 = wp[t + 2], w3 = wp[t + 3];
        p0 = fmaf(w0, f0.x, p0); p1 = fmaf(w0, f0.y, p1);
        q0 = fmaf(w1, f1.x, q0); q1 = fmaf(w1, f1.y, q1);
        r0 = fmaf(w2, f2.x, r0); r1 = fmaf(w2, f2.y, r1);
        u0 = fmaf(w3, f3.x, u0); u1 = fmaf(w3, f3.y, u1);
    }
    g_ctxP[x][b * S + d0]     = (p0 + q0) + (r0 + u0);
    g_ctxP[x][b * S + d0 + 1] = (p1 + q1) + (r1 + u1);
}

// ---------------- launch ----------------
extern "C" void kernel_launch(void* const* d_in, const int* in_sizes, int n_in,
                              void* d_out, int out_size) {
    const int*   input    = (const int*)d_in[0];
    const float* features = (const float*)d_in[1];
    const float* emb      = (const float*)d_in[2];
    const float* W_ih     = (const float*)d_in[3];
    const float* W_hh     = (const float*)d_in[4];
    const float* b_ih     = (const float*)d_in[5];
    const float* b_hh     = (const float*)d_in[6];
    const float* Wq       = (const float*)d_in[7];
    const float* bq       = (const float*)d_in[8];
    const float* Wk       = (const float*)d_in[9];
    const float* bk       = (const float*)d_in[10];
    const float* conv_w   = (const float*)d_in[11];
    const float* conv_b   = (const float*)d_in[12];
    const float* v_vec    = (const float*)d_in[13];
    const float* Wo       = (const float*)d_in[14];
    const float* bo       = (const float*)d_in[15];

    float* outs = (float*)d_out;                        // [B, TD, V]
    float* ws   = outs + (size_t)B * TD * V;            // [B, TD, TF]

    init_kernel<<<(B * TF + 255) / 256, 256>>>();
    cw_transpose_kernel<<<(S * KW + 255) / 256, 256>>>(conv_w, bq, conv_b);
    feat_convert_kernel<<<(int)(((size_t)B * TF * S / 4) / 256), 256>>>(features);
    keys_gemm_kernel<<<dim3((B * TF) / 64, S / 64), 256>>>(features, Wk, bk);

    // prologue: gate partials for t=0 (h_{-1}=0 via zeroed hbuf, ctx=0 via zeroed ctxP)
    gemm64_kernel<<<dim3(24, 12), 256>>>(0, input, emb, W_ih, W_hh, Wo, 0, 1);

    for (int t = 0; t < TD; ++t) {
        // h_t from gate partials + q partials + finalize logits of t-1
        hq_kernel<<<dim3(9, 8), 256>>>(Wq, outs, bo, b_ih, b_hh, t - 1, t & 1);
        scores_kernel<<<dim3(TF / (TT * NTILE), B), 256>>>(v_vec);
        ctxsm_kernel<<<dim3(4, B), 256>>>(ws, t);
        if (t < TD - 1) {
            // combined: gates t+1 (y 0..11) + logits partials t (y 12..19)
            gemm64_kernel<<<dim3(24, 20), 256>>>(0, input, emb, W_ih, W_hh, Wo, t + 1, t & 1);
        } else {
            gemm64_kernel<<<dim3(16, 8), 256>>>(3, input, emb, W_ih, W_hh, Wo, t, t & 1);
        }
    }
    // epilogue: finalize logits of final step
    logits_fin_kernel<<<128, 256>>>(outs, bo);
}